// round 6
// baseline (speedup 1.0000x reference)
#include <cuda_runtime.h>
#include <math.h>

#define BATCH 4
#define DIMC  64
#define HFC   128
#define C2C   256
#define HH    256
#define WWC   256
#define HW    (HH*WWC)   // 65536

typedef unsigned long long u64;

// ---------------- scratch (device globals: allocation-free rule) -------------
__device__ float g_u[(size_t)BATCH*C2C*HW];           // spectral output (268 MB)
__device__ float g_g[(size_t)BATCH*HFC*HW];           // gated output    (134 MB)
__device__ u64   g_pk[(size_t)C2C*8*32];              // packed spatial filter pairs
__device__ u64   g_wi[8*64*16];                       // packed w_in  per oc-group
__device__ u64   g_wo[128*32];                        // packed w_out

// ---------------- packed fp32x2 helpers (sm_100+ PTX) ------------------------
__device__ __forceinline__ u64 pk(float lo, float hi){
    u64 r; asm("mov.b64 %0, {%1,%2};" : "=l"(r) : "f"(lo), "f"(hi)); return r;
}
__device__ __forceinline__ float2 upk(u64 v){
    float2 r; asm("mov.b64 {%0,%1}, %2;" : "=f"(r.x), "=f"(r.y) : "l"(v)); return r;
}
__device__ __forceinline__ void fma2(u64& d, u64 a, u64 b){
    asm("fma.rn.f32x2 %0, %1, %2, %0;" : "+l"(d) : "l"(a), "l"(b));
}

// ---------------- K0: spectral filter -> packed spatial 8x8 kernels ----------
// g_c[n1,n2] = (1/64) * sum_{k1,k2} G(k1,k2) cos(pi/4*(k1*n1+k2*n2)),
// G = Hermitian extension of F with symmetrization at k2 in {0,4}.
// g_pk[c][n2][a*4+q] = ( g[a][(n2-2q)&7], g[a][(n2-2q-1)&7] )
__global__ void k0_spectral(const float* __restrict__ filt){
    __shared__ float gs[64];
    int c = blockIdx.x, t = threadIdx.x;
    int n1 = t >> 3, n2 = t & 7;
    const float* F = filt + c*40;   // [8][5]
    float s = 0.f;
    for (int k1=0;k1<8;k1++){
        for (int k2=0;k2<8;k2++){
            float Gv;
            if (k2>=1 && k2<=3)      Gv = F[k1*5+k2];
            else if (k2>=5)          Gv = F[((8-k1)&7)*5 + (8-k2)];
            else                     Gv = 0.5f*(F[k1*5+k2] + F[((8-k1)&7)*5 + k2]);
            int m = (k1*n1 + k2*n2) & 7;
            s += Gv * cospif(0.25f * (float)m);
        }
    }
    gs[t] = s * (1.f/64.f);
    __syncthreads();
    for (int r=0;r<4;r++){
        int idx = r*64 + t;           // 0..255
        int nn2 = idx >> 5;
        int aq  = idx & 31;
        int a = aq >> 2, q = aq & 3;
        g_pk[((size_t)c*8 + nn2)*32 + aq] =
            pk(gs[a*8 + ((nn2-2*q)&7)], gs[a*8 + ((nn2-2*q-1)&7)]);
    }
}

// ---------------- K0b: pack projection weights -------------------------------
__global__ void k0_packw(const float* __restrict__ w_in, const float* __restrict__ w_out){
    int idx = blockIdx.x*256 + threadIdx.x;
    // g_wi[ocg][c][j] = (w_in[ocg*32+2j][c], w_in[ocg*32+2j+1][c])
    if (idx < 8*64*16){
        int ocg = idx >> 10, c = (idx >> 4) & 63, j = idx & 15;
        int o = ocg*32 + 2*j;
        g_wi[idx] = pk(w_in[o*DIMC + c], w_in[(o+1)*DIMC + c]);
    }
    // g_wo[ii][j] = (w_out[2j][ii], w_out[2j+1][ii])
    if (idx < 128*32){
        int ii = idx >> 5, j = idx & 31;
        g_wo[idx] = pk(w_out[(2*j)*HFC + ii], w_out[(2*j+1)*HFC + ii]);
    }
}

// ---------------- K12: fused in-projection + patchwise circular conv ---------
// grid (ocg=8, tile=128, b=4): ocg fastest -> 8 blocks sharing an x strip are
// wave-adjacent (L2 reuse). Block: 8x64 spatial strip (512 px), 32 oc.
__global__ __launch_bounds__(256, 2) void k12_fused(const float* __restrict__ x){
    extern __shared__ float sm[];
    float* xs = sm;                       // [32][512] (64KB), aliased as hs[32][8][64]
    int oc0 = blockIdx.x*32;
    int tile = blockIdx.y; int s = tile>>2, cg = tile&3;
    int b = blockIdx.z;
    int t = threadIdx.x;

    const u64* wtab = &g_wi[(size_t)blockIdx.x*64*16];   // [64][16] L1-resident

    int pxt = t & 127, ocg2 = t >> 7;           // 128 px-threads x 2 oc-subgroups
    int row = pxt >> 4, col4 = (pxt & 15) * 4;
    u64 acc[4][8];
    #pragma unroll
    for (int p=0;p<4;p++)
        #pragma unroll
        for (int j=0;j<8;j++) acc[p][j]=0ULL;

    const float* xb = x + (size_t)b*DIMC*HW + (s*8)*WWC + cg*64;
    for (int kc=0; kc<2; kc++){
        __syncthreads();
        for (int idx=t; idx<32*512; idx+=256){
            int c = idx>>9, px = idx&511, r = px>>6, cl = px&63;
            xs[idx] = xb[(size_t)(kc*32+c)*HW + r*WWC + cl];
        }
        __syncthreads();
        #pragma unroll 4
        for (int c=0;c<32;c++){
            float4 xv = *(const float4*)&xs[c*512 + pxt*4];
            u64 xp0 = pk(xv.x,xv.x), xp1 = pk(xv.y,xv.y);
            u64 xp2 = pk(xv.z,xv.z), xp3 = pk(xv.w,xv.w);
            const u64* wr = &wtab[(kc*32+c)*16 + ocg2*8];
            #pragma unroll
            for (int j=0;j<8;j++){
                u64 w = __ldg(&wr[j]);
                fma2(acc[0][j], xp0, w);
                fma2(acc[1][j], xp1, w);
                fma2(acc[2][j], xp2, w);
                fma2(acc[3][j], xp3, w);
            }
        }
    }
    __syncthreads();   // GEMM reads done before aliasing xs as hs

    float* hs = xs;    // hs[ocl][row][col]
    #pragma unroll
    for (int j=0;j<8;j++){
        int ocl0 = ocg2*16 + 2*j;
        float2 v0=upk(acc[0][j]), v1=upk(acc[1][j]), v2=upk(acc[2][j]), v3=upk(acc[3][j]);
        *(float4*)&hs[(ocl0*8 + row)*64 + col4]     = make_float4(v0.x, v1.x, v2.x, v3.x);
        *(float4*)&hs[((ocl0+1)*8 + row)*64 + col4] = make_float4(v0.y, v1.y, v2.y, v3.y);
    }
    __syncthreads();

    // Phase 2: per-channel 8x8 circular conv, a-outer with filter prefetch.
    int chq = t >> 6;                 // 0..3
    int colc = t & 63;
    int n2 = colc & 7, p8 = (colc >> 3) * 8;
    float* ub = g_u + (size_t)(b*C2C + oc0)*HW + (s*8)*WWC + cg*64;
    for (int it=0; it<8; it++){
        int chl = it*4 + chq;         // local channel 0..31
        const ulonglong2* gptr = (const ulonglong2*)&g_pk[((size_t)(oc0+chl)*8 + n2)*32];
        u64 xq[32];
        #pragma unroll
        for (int m1=0;m1<8;m1++)
            #pragma unroll
            for (int q=0;q<4;q++)
                xq[m1*4+q] = *(const u64*)&hs[(chl*8+m1)*64 + p8 + 2*q];
        u64 acc2[8];
        #pragma unroll
        for (int n=0;n<8;n++) acc2[n]=0ULL;
        ulonglong2 gA = __ldg(&gptr[0]), gB = __ldg(&gptr[1]);
        #pragma unroll
        for (int a=0;a<8;a++){
            u64 g0=gA.x, g1=gA.y, g2=gB.x, g3=gB.y;
            if (a<7){ gA = __ldg(&gptr[(a+1)*2]); gB = __ldg(&gptr[(a+1)*2+1]); }
            #pragma unroll
            for (int m1=0;m1<8;m1++){
                int n1 = (m1+a)&7;
                fma2(acc2[n1], xq[m1*4+0], g0);
                fma2(acc2[n1], xq[m1*4+1], g1);
                fma2(acc2[n1], xq[m1*4+2], g2);
                fma2(acc2[n1], xq[m1*4+3], g3);
            }
        }
        #pragma unroll
        for (int n1=0;n1<8;n1++){
            float2 v = upk(acc2[n1]);
            ub[(size_t)chl*HW + n1*WWC + colc] = v.x + v.y;
        }
    }
}

// ---------------- K3: depthwise 3x3 (SAME) + exact GELU gate -----------------
__global__ __launch_bounds__(256) void k3_dwgelu(const float* __restrict__ w_dw){
    __shared__ float su[2][18][258];
    int yt = blockIdx.x, i = blockIdx.y, b = blockIdx.z;
    int t = threadIdx.x;
    int y0 = yt*16;
    const float* u1 = g_u + (size_t)(b*C2C + i)*HW;
    const float* u2 = g_u + (size_t)(b*C2C + i + HFC)*HW;
    for (int rr=0; rr<18; rr++){
        int y = y0 + rr - 1;
        bool ok = (y>=0 && y<HH);
        su[0][rr][t+1] = ok ? u1[y*WWC + t] : 0.f;
        su[1][rr][t+1] = ok ? u2[y*WWC + t] : 0.f;
    }
    if (t < 18){ su[0][t][0]=0.f; su[0][t][257]=0.f; su[1][t][0]=0.f; su[1][t][257]=0.f; }
    __syncthreads();
    float wA[9], wB[9];
    #pragma unroll
    for (int k=0;k<9;k++){ wA[k]=w_dw[i*9+k]; wB[k]=w_dw[(i+HFC)*9+k]; }
    float* gb = g_g + (size_t)(b*HFC + i)*HW;
    for (int r=0;r<16;r++){
        float d1=0.f, d2=0.f;
        #pragma unroll
        for (int dy=0;dy<3;dy++){
            #pragma unroll
            for (int dx=0;dx<3;dx++){
                d1 = fmaf(wA[dy*3+dx], su[0][r+dy][t+dx], d1);
                d2 = fmaf(wB[dy*3+dx], su[1][r+dy][t+dx], d2);
            }
        }
        float ge = 0.5f*d1*(1.f + erff(d1*0.70710678118654752f));
        gb[(y0+r)*WWC + t] = ge*d2;
    }
}

// ---------------- K4: out-projection (register-tiled GEMM) -------------------
// 2048 blocks: 128-px tile x 4 batch. Thread: 4 px x 8 oc. Weights via L1.
__global__ __launch_bounds__(256) void k4_outproj(float* __restrict__ out){
    __shared__ float gs[32*128];         // 16KB
    int b = blockIdx.y; int px0 = blockIdx.x*128;
    int t = threadIdx.x;
    int pxt = t & 31, ocg = t >> 5;      // 32 px-threads x 8 oc-groups (4 pairs each)
    u64 acc[4][4];
    #pragma unroll
    for (int p=0;p<4;p++)
        #pragma unroll
        for (int j=0;j<4;j++) acc[p][j]=0ULL;

    const float* gb = g_g + (size_t)b*HFC*HW + px0;
    for (int kc=0;kc<4;kc++){
        __syncthreads();
        for (int idx=t; idx<32*128; idx+=256){
            int ii = idx>>7, p = idx&127;
            gs[idx] = gb[(size_t)(kc*32+ii)*HW + p];
        }
        __syncthreads();
        #pragma unroll 4
        for (int ii=0; ii<32; ii++){
            float4 xv = *(const float4*)&gs[ii*128 + pxt*4];
            u64 xp0 = pk(xv.x,xv.x), xp1 = pk(xv.y,xv.y);
            u64 xp2 = pk(xv.z,xv.z), xp3 = pk(xv.w,xv.w);
            const u64* wr = &g_wo[(kc*32+ii)*32 + ocg*4];
            #pragma unroll
            for (int j=0;j<4;j++){
                u64 w = __ldg(&wr[j]);
                fma2(acc[0][j], xp0, w);
                fma2(acc[1][j], xp1, w);
                fma2(acc[2][j], xp2, w);
                fma2(acc[3][j], xp3, w);
            }
        }
    }
    float* ob = out + (size_t)b*DIMC*HW + px0;
    #pragma unroll
    for (int j=0;j<4;j++){
        int jj = ocg*4 + j;
        float2 v0=upk(acc[0][j]), v1=upk(acc[1][j]), v2=upk(acc[2][j]), v3=upk(acc[3][j]);
        *(float4*)&ob[(size_t)(2*jj)*HW   + pxt*4] = make_float4(v0.x, v1.x, v2.x, v3.x);
        *(float4*)&ob[(size_t)(2*jj+1)*HW + pxt*4] = make_float4(v0.y, v1.y, v2.y, v3.y);
    }
}

// -----------------------------------------------------------------------------
extern "C" void kernel_launch(void* const* d_in, const int* in_sizes, int n_in,
                              void* d_out, int out_size){
    const float* x     = (const float*)d_in[0];
    const float* w_in  = (const float*)d_in[1];
    const float* w_dw  = (const float*)d_in[2];
    const float* filt  = (const float*)d_in[3];
    const float* w_out = (const float*)d_in[4];
    float* out = (float*)d_out;

    const int smem12 = 32*512*4;               // 65536 B
    cudaFuncSetAttribute(k12_fused, cudaFuncAttributeMaxDynamicSharedMemorySize, smem12);

    k0_spectral<<<256, 64>>>(filt);
    k0_packw   <<<32, 256>>>(w_in, w_out);
    k12_fused  <<<dim3(8,128,4), 256, smem12>>>(x);
    k3_dwgelu  <<<dim3(16,128,4), 256>>>(w_dw);
    k4_outproj <<<dim3(512,4),    256>>>(out);
}